// round 2
// baseline (speedup 1.0000x reference)
#include <cuda_runtime.h>
#include <cstdint>

#define SEQ 512
#define BS 64
#define IN_DIM 1024
#define HDIM 1024
#define G4 4096           // 4 gates * H, packed as [k][j*4 + gate]
#define KD 1024
#define NCTA 128
#define NTHR 256

// ---------------- device scratch (allocation rules forbid cudaMalloc) -----------
__device__ float g_Wx0[IN_DIM * G4];
__device__ float g_Wx1[HDIM * G4];
__device__ float g_Wh [HDIM * G4];
__device__ float g_bias[G4];
__device__ float g_xw [(size_t)SEQ * BS * G4];    // X@W + b for current layer
__device__ float g_seq0[(size_t)SEQ * BS * HDIM]; // layer0 output sequence
__device__ float g_hA[BS * HDIM];
__device__ float g_hB[BS * HDIM];
__device__ float g_c [BS * HDIM];

// grid barrier state (zero-initialized; invariant: returns to 0 after each launch
// because the barrier count per launch is even)
__device__ unsigned g_bcount;
__device__ volatile unsigned g_bsense;

// ---------------- helpers -------------------------------------------------------
__device__ __forceinline__ unsigned f2tf(float x) {
    unsigned u;
    asm("cvt.rna.tf32.f32 %0, %1;" : "=r"(u) : "f"(x));
    return u;
}

__device__ __forceinline__ void mma_tf32(float& c0, float& c1, float& c2, float& c3,
                                         unsigned a0, unsigned a1, unsigned a2, unsigned a3,
                                         unsigned b0, unsigned b1) {
    asm volatile(
        "mma.sync.aligned.m16n8k8.row.col.f32.tf32.tf32.f32 "
        "{%0,%1,%2,%3}, {%4,%5,%6,%7}, {%8,%9}, {%0,%1,%2,%3};"
        : "+f"(c0), "+f"(c1), "+f"(c2), "+f"(c3)
        : "r"(a0), "r"(a1), "r"(a2), "r"(a3), "r"(b0), "r"(b1));
}

__device__ __forceinline__ float sigmoidf_(float x) {
    return 1.0f / (1.0f + __expf(-x));
}

// ---------------- weight / bias packing ------------------------------------------
__global__ void pack_w(const float* __restrict__ Wi, const float* __restrict__ Wf,
                       const float* __restrict__ Wg, const float* __restrict__ Wo,
                       float* __restrict__ dst, int K) {
    int idx = blockIdx.x * blockDim.x + threadIdx.x;
    if (idx >= K * HDIM) return;
    float4 v;
    v.x = __uint_as_float(f2tf(Wi[idx]));
    v.y = __uint_as_float(f2tf(Wf[idx]));
    v.z = __uint_as_float(f2tf(Wg[idx]));
    v.w = __uint_as_float(f2tf(Wo[idx]));
    reinterpret_cast<float4*>(dst)[idx] = v;
}

__global__ void pack_b(const float* __restrict__ bi, const float* __restrict__ bf,
                       const float* __restrict__ bg, const float* __restrict__ bo,
                       float* __restrict__ dst) {
    int j = blockIdx.x * blockDim.x + threadIdx.x;
    if (j >= HDIM) return;
    float4 v;
    v.x = bi[j]; v.y = bf[j]; v.z = bg[j]; v.w = bo[j];
    reinterpret_cast<float4*>(dst)[j] = v;
}

// ---------------- big input-projection GEMM --------------------------------------
#define XBM 128
#define XBN 128
#define XBK 32

__global__ void __launch_bounds__(256)
gemm_xw(const float* __restrict__ A, const float* __restrict__ Bp,
        float* __restrict__ C, const float* __restrict__ bias) {
    __shared__ float As[XBM][XBK + 1];
    __shared__ float Bs[XBK][XBN + 4];

    const int m0 = blockIdx.y * XBM;
    const int n0 = blockIdx.x * XBN;
    const int tid  = threadIdx.x;
    const int warp = tid >> 5, lane = tid & 31;
    const int grp  = lane >> 2, tg = lane & 3;
    const int wm = warp & 3;
    const int wn = warp >> 2;

    float acc[2][8][4];
#pragma unroll
    for (int mt = 0; mt < 2; mt++)
#pragma unroll
        for (int nt = 0; nt < 8; nt++)
#pragma unroll
            for (int q = 0; q < 4; q++) acc[mt][nt][q] = 0.0f;

    for (int kb = 0; kb < KD; kb += XBK) {
#pragma unroll
        for (int it = 0; it < 4; it++) {
            int v = tid + it * 256;
            int r = v >> 3, c4 = (v & 7) << 2;
            float4 f = *reinterpret_cast<const float4*>(A + (size_t)(m0 + r) * KD + kb + c4);
            As[r][c4 + 0] = __uint_as_float(f2tf(f.x));
            As[r][c4 + 1] = __uint_as_float(f2tf(f.y));
            As[r][c4 + 2] = __uint_as_float(f2tf(f.z));
            As[r][c4 + 3] = __uint_as_float(f2tf(f.w));
        }
#pragma unroll
        for (int it = 0; it < 4; it++) {
            int v = tid + it * 256;
            int r = v >> 5, c4 = (v & 31) << 2;
            float4 f = *reinterpret_cast<const float4*>(Bp + (size_t)(kb + r) * G4 + n0 + c4);
            Bs[r][c4 + 0] = f.x;
            Bs[r][c4 + 1] = f.y;
            Bs[r][c4 + 2] = f.z;
            Bs[r][c4 + 3] = f.w;
        }
        __syncthreads();

#pragma unroll
        for (int kk = 0; kk < 4; kk++) {
            const int ks = kk * 8;
            unsigned a[2][4], b[8][2];
#pragma unroll
            for (int mt = 0; mt < 2; mt++) {
                int r = wm * 32 + mt * 16 + grp;
                a[mt][0] = __float_as_uint(As[r    ][ks + tg    ]);
                a[mt][1] = __float_as_uint(As[r + 8][ks + tg    ]);
                a[mt][2] = __float_as_uint(As[r    ][ks + tg + 4]);
                a[mt][3] = __float_as_uint(As[r + 8][ks + tg + 4]);
            }
#pragma unroll
            for (int nt = 0; nt < 8; nt++) {
                int c = wn * 64 + nt * 8 + grp;
                b[nt][0] = __float_as_uint(Bs[ks + tg    ][c]);
                b[nt][1] = __float_as_uint(Bs[ks + tg + 4][c]);
            }
#pragma unroll
            for (int mt = 0; mt < 2; mt++)
#pragma unroll
                for (int nt = 0; nt < 8; nt++)
                    mma_tf32(acc[mt][nt][0], acc[mt][nt][1], acc[mt][nt][2], acc[mt][nt][3],
                             a[mt][0], a[mt][1], a[mt][2], a[mt][3],
                             b[nt][0], b[nt][1]);
        }
        __syncthreads();
    }

#pragma unroll
    for (int mt = 0; mt < 2; mt++) {
        int r = m0 + wm * 32 + mt * 16 + grp;
#pragma unroll
        for (int nt = 0; nt < 8; nt++) {
            int c = n0 + wn * 64 + nt * 8 + tg * 2;
            float2 bv = *reinterpret_cast<const float2*>(bias + c);
            float2 o0, o1;
            o0.x = acc[mt][nt][0] + bv.x;  o0.y = acc[mt][nt][1] + bv.y;
            o1.x = acc[mt][nt][2] + bv.x;  o1.y = acc[mt][nt][3] + bv.y;
            *reinterpret_cast<float2*>(C + (size_t)r * G4 + c)       = o0;
            *reinterpret_cast<float2*>(C + (size_t)(r + 8) * G4 + c) = o1;
        }
    }
}

// ---------------- persistent recurrent layer -------------------------------------
// 128 CTAs x 256 threads, 1 CTA/SM. Each CTA owns 32 packed gate columns
// (8 hidden units). W_h slice lives in SMEM for all 512 steps; c in registers.
// h ping-pongs in global memory; grid barrier between steps.
//
// SMEM: Wt[32][1032] + As[2][64][68] + Cs[64][36]  = 176128 B dynamic.
#define WT_STRIDE 1032
#define AS_STRIDE 68
#define CS_STRIDE 36
#define SMEM_FLOATS (32 * WT_STRIDE + 2 * 64 * AS_STRIDE + 64 * CS_STRIDE)

__device__ __forceinline__ void grid_bar(unsigned& sense) {
    __syncthreads();
    sense ^= 1u;
    if (threadIdx.x == 0) {
        __threadfence();
        if (atomicAdd(&g_bcount, 1u) == NCTA - 1) {
            g_bcount = 0;             // reset before release; spinners watch sense
            __threadfence();
            g_bsense = sense;
        } else {
            while (g_bsense != sense) { __nanosleep(32); }
        }
        __threadfence();
    }
    __syncthreads();
}

__global__ void __launch_bounds__(NTHR, 1)
lstm_layer(const float* __restrict__ xw, float* __restrict__ h0,
           float* __restrict__ h1, float* __restrict__ cdump,
           float* __restrict__ seq_out) {
    extern __shared__ float smem[];
    float* Wt = smem;                        // [32][WT_STRIDE]  Wt[c][k]
    float* As = Wt + 32 * WT_STRIDE;         // [2][64][AS_STRIDE]
    float* Cs = As + 2 * 64 * AS_STRIDE;     // [64][CS_STRIDE]

    const int tid  = threadIdx.x;
    const int warp = tid >> 5, lane = tid & 31;
    const int grp  = lane >> 2, tg = lane & 3;
    const int mt = warp & 3;                 // M16 tile (rows mt*16..)
    const int nh = warp >> 2;                // N16 half

    const int n0 = blockIdx.x * 32;          // packed gate column base
    const int J0 = blockIdx.x * 8;           // hidden-unit base

    // ---- preload W_h slice into SMEM (transposed: Wt[c][k]) ----
    for (int idx = tid; idx < 32 * 1024 / 4; idx += NTHR) {
        int k  = idx >> 3;
        int c4 = (idx & 7) << 2;
        float4 f = *reinterpret_cast<const float4*>(g_Wh + (size_t)k * G4 + n0 + c4);
        Wt[(c4 + 0) * WT_STRIDE + k] = f.x;
        Wt[(c4 + 1) * WT_STRIDE + k] = f.y;
        Wt[(c4 + 2) * WT_STRIDE + k] = f.z;
        Wt[(c4 + 3) * WT_STRIDE + k] = f.w;
    }

    // ---- zero h (own columns, both buffers) ----
    for (int idx = tid; idx < 512; idx += NTHR) {
        int b = idx >> 3, j = idx & 7;
        h0[b * HDIM + J0 + j] = 0.0f;
        h1[b * HDIM + J0 + j] = 0.0f;
    }

    unsigned sense = 0;
    grid_bar(sense);                         // barrier #1 (init)

    float creg[2] = {0.0f, 0.0f};
    float* hbuf[2] = {h0, h1};

    for (int s = 0; s < SEQ; s++) {
        const float* __restrict__ hr = hbuf[s & 1];
        float* __restrict__ hw = hbuf[(s + 1) & 1];

        float acc[2][4];
#pragma unroll
        for (int nt = 0; nt < 2; nt++)
#pragma unroll
            for (int q = 0; q < 4; q++) acc[nt][q] = 0.0f;

        // prologue: load chunk 0 (64 batch x 64 k)
        float4 pf[4];
#pragma unroll
        for (int i = 0; i < 4; i++) {
            int idx = tid + i * NTHR;
            int r = idx >> 4, c4 = (idx & 15) << 2;
            pf[i] = *reinterpret_cast<const float4*>(hr + (size_t)r * KD + c4);
        }
#pragma unroll
        for (int i = 0; i < 4; i++) {
            int idx = tid + i * NTHR;
            int r = idx >> 4, c4 = (idx & 15) << 2;
            *reinterpret_cast<float4*>(As + (size_t)r * AS_STRIDE + c4) = pf[i];
        }
        __syncthreads();

        for (int kb = 0; kb < 16; kb++) {
            const int cur = kb & 1;
            const float* Ab = As + (size_t)cur * 64 * AS_STRIDE;
            const int kbase = kb * 64;

            if (kb < 15) {
#pragma unroll
                for (int i = 0; i < 4; i++) {
                    int idx = tid + i * NTHR;
                    int r = idx >> 4, c4 = (idx & 15) << 2;
                    pf[i] = *reinterpret_cast<const float4*>(
                        hr + (size_t)r * KD + kbase + 64 + c4);
                }
            }

#pragma unroll
            for (int kk = 0; kk < 8; kk++) {
                const int ks = kk * 8;
                const int r = mt * 16 + grp;
                unsigned a0 = __float_as_uint(Ab[(r    ) * AS_STRIDE + ks + tg    ]);
                unsigned a1 = __float_as_uint(Ab[(r + 8) * AS_STRIDE + ks + tg    ]);
                unsigned a2 = __float_as_uint(Ab[(r    ) * AS_STRIDE + ks + tg + 4]);
                unsigned a3 = __float_as_uint(Ab[(r + 8) * AS_STRIDE + ks + tg + 4]);
#pragma unroll
                for (int nt = 0; nt < 2; nt++) {
                    const int c = nh * 16 + nt * 8 + grp;
                    unsigned b0 = __float_as_uint(Wt[c * WT_STRIDE + kbase + ks + tg    ]);
                    unsigned b1 = __float_as_uint(Wt[c * WT_STRIDE + kbase + ks + tg + 4]);
                    mma_tf32(acc[nt][0], acc[nt][1], acc[nt][2], acc[nt][3],
                             a0, a1, a2, a3, b0, b1);
                }
            }

            if (kb < 15) {
                float* An = As + (size_t)(1 - cur) * 64 * AS_STRIDE;
#pragma unroll
                for (int i = 0; i < 4; i++) {
                    int idx = tid + i * NTHR;
                    int r = idx >> 4, c4 = (idx & 15) << 2;
                    *reinterpret_cast<float4*>(An + (size_t)r * AS_STRIDE + c4) = pf[i];
                }
            }
            __syncthreads();
        }

        // spill accumulators: Cs[row][col]
        {
            const int r = mt * 16 + grp;
#pragma unroll
            for (int nt = 0; nt < 2; nt++) {
                const int c = nh * 16 + nt * 8 + tg * 2;
                Cs[(r    ) * CS_STRIDE + c    ] = acc[nt][0];
                Cs[(r    ) * CS_STRIDE + c + 1] = acc[nt][1];
                Cs[(r + 8) * CS_STRIDE + c    ] = acc[nt][2];
                Cs[(r + 8) * CS_STRIDE + c + 1] = acc[nt][3];
            }
        }
        __syncthreads();

        // pointwise LSTM update (2 items/thread)
        const float* xw_t = xw + (size_t)s * BS * G4;
        float* so = seq_out + (size_t)s * BS * HDIM;
#pragma unroll
        for (int it = 0; it < 2; it++) {
            int idx = tid + it * NTHR;       // 0..511
            int b = idx >> 3, j = idx & 7;
            int col = j << 2;
            float4 xv = *reinterpret_cast<const float4*>(xw_t + (size_t)b * G4 + n0 + col);
            float pi = Cs[b * CS_STRIDE + col + 0] + xv.x;
            float pfv = Cs[b * CS_STRIDE + col + 1] + xv.y;
            float pg = Cs[b * CS_STRIDE + col + 2] + xv.z;
            float po = Cs[b * CS_STRIDE + col + 3] + xv.w;

            float gi = sigmoidf_(pi);
            float gf = sigmoidf_(pfv);
            float gg = tanhf(pg);
            float go = sigmoidf_(po);

            float cv = gf * creg[it] + gi * gg;
            creg[it] = cv;
            float hv = go * tanhf(cv);

            int hi = b * HDIM + J0 + j;
            hw[hi] = __uint_as_float(f2tf(hv));   // tf32-rounded for next step MMA
            so[hi] = hv;                           // full-precision output
            if (s == SEQ - 1) cdump[hi] = cv;
        }

        if (s < SEQ - 1) grid_bar(sense);     // barriers #2..#512 (total even)
    }
}

// ---------------- tail: (h, c) after the sequence --------------------------------
__global__ void copy_tail(const float* __restrict__ hsrc, const float* __restrict__ csrc,
                          float* __restrict__ dst) {
    int i = blockIdx.x * blockDim.x + threadIdx.x;
    if (i < BS * HDIM) {
        dst[i] = hsrc[i];
        dst[BS * HDIM + i] = csrc[i];
    }
}

// ---------------- launcher --------------------------------------------------------
extern "C" void kernel_launch(void* const* d_in, const int* in_sizes, int n_in,
                              void* d_out, int out_size) {
    (void)in_sizes; (void)n_in;

    const float* x     = (const float*)d_in[0];
    const float* Wii0  = (const float*)d_in[1];
    const float* Wii   = (const float*)d_in[2];
    const float* Whi   = (const float*)d_in[3];
    const float* Wif0  = (const float*)d_in[4];
    const float* Wif   = (const float*)d_in[5];
    const float* Whf   = (const float*)d_in[6];
    const float* Wig0  = (const float*)d_in[7];
    const float* Wig   = (const float*)d_in[8];
    const float* Whg   = (const float*)d_in[9];
    const float* Wio0  = (const float*)d_in[10];
    const float* Wio   = (const float*)d_in[11];
    const float* Who   = (const float*)d_in[12];
    const float* bi    = (const float*)d_in[13];
    const float* bf    = (const float*)d_in[14];
    const float* bg    = (const float*)d_in[15];
    const float* bo    = (const float*)d_in[16];

    float *pWx0, *pWx1, *pWh, *pBias, *pXw, *pSeq0, *pHA, *pHB, *pC;
    cudaGetSymbolAddress((void**)&pWx0,  g_Wx0);
    cudaGetSymbolAddress((void**)&pWx1,  g_Wx1);
    cudaGetSymbolAddress((void**)&pWh,   g_Wh);
    cudaGetSymbolAddress((void**)&pBias, g_bias);
    cudaGetSymbolAddress((void**)&pXw,   g_xw);
    cudaGetSymbolAddress((void**)&pSeq0, g_seq0);
    cudaGetSymbolAddress((void**)&pHA,   g_hA);
    cudaGetSymbolAddress((void**)&pHB,   g_hB);
    cudaGetSymbolAddress((void**)&pC,    g_c);

    float* out = (float*)d_out;

    static bool attr_set = false;
    if (!attr_set) {
        cudaFuncSetAttribute(lstm_layer, cudaFuncAttributeMaxDynamicSharedMemorySize,
                             SMEM_FLOATS * (int)sizeof(float));
        attr_set = true;
    }

    // pack weights / bias
    {
        int n = IN_DIM * HDIM;
        pack_w<<<(n + 255) / 256, 256>>>(Wii0, Wif0, Wig0, Wio0, pWx0, IN_DIM);
        n = HDIM * HDIM;
        pack_w<<<(n + 255) / 256, 256>>>(Wii,  Wif,  Wig,  Wio,  pWx1, HDIM);
        pack_w<<<(n + 255) / 256, 256>>>(Whi,  Whf,  Whg,  Who,  pWh,  HDIM);
        pack_b<<<(HDIM + 255) / 256, 256>>>(bi, bf, bg, bo, pBias);
    }

    const dim3 gemm_grid(G4 / XBN, (SEQ * BS) / XBM);  // (32, 256)
    const size_t smem_bytes = SMEM_FLOATS * sizeof(float);

    // ---------------- layer 0 ----------------
    gemm_xw<<<gemm_grid, 256>>>(x, pWx0, pXw, pBias);
    lstm_layer<<<NCTA, NTHR, smem_bytes>>>(pXw, pHA, pHB, pC, pSeq0);

    // ---------------- layer 1 ----------------
    gemm_xw<<<gemm_grid, 256>>>(pSeq0, pWx1, pXw, pBias);
    lstm_layer<<<NCTA, NTHR, smem_bytes>>>(pXw, pHA, pHB, pC, out);

    // tail: final (h, c). h final = seq output at t = SEQ-1 (full precision).
    size_t seqN = (size_t)SEQ * BS * HDIM;
    if ((size_t)out_size >= seqN + 2 * (size_t)BS * HDIM) {
        copy_tail<<<(BS * HDIM + 255) / 256, 256>>>(out + seqN - (size_t)BS * HDIM,
                                                    pC, out + seqN);
    }
}

// round 3
// speedup vs baseline: 1.4442x; 1.4442x over previous
#include <cuda_runtime.h>
#include <cstdint>

#define SEQ 512
#define BS 64
#define IN_DIM 1024
#define HDIM 1024
#define G4 4096           // 4 gates * H, packed as [k][j*4 + gate]
#define KD 1024
#define NCTA 128
#define NTHR 256

// ---------------- device scratch (allocation rules forbid cudaMalloc) -----------
__device__ float g_Wx0[IN_DIM * G4];
__device__ float g_Wx1[HDIM * G4];
__device__ float g_Wh [HDIM * G4];
__device__ float g_bias[G4];
__device__ float g_xw [(size_t)SEQ * BS * G4];    // X@W + b for current layer
__device__ float g_seq0[(size_t)SEQ * BS * HDIM]; // layer0 output sequence
__device__ float g_hA[BS * HDIM];                 // h ping-pong (k-PERMUTED layout)
__device__ float g_hB[BS * HDIM];
__device__ float g_c [BS * HDIM];

// grid barrier state (zero-init; count per launch is even so sense returns to 0)
__device__ unsigned g_bcount;
__device__ volatile unsigned g_bsense;

// ---------------- helpers -------------------------------------------------------
__device__ __forceinline__ unsigned f2tf(float x) {
    unsigned u;
    asm("cvt.rna.tf32.f32 %0, %1;" : "=r"(u) : "f"(x));
    return u;
}

__device__ __forceinline__ void mma_tf32(float& c0, float& c1, float& c2, float& c3,
                                         unsigned a0, unsigned a1, unsigned a2, unsigned a3,
                                         unsigned b0, unsigned b1) {
    asm volatile(
        "mma.sync.aligned.m16n8k8.row.col.f32.tf32.tf32.f32 "
        "{%0,%1,%2,%3}, {%4,%5,%6,%7}, {%8,%9}, {%0,%1,%2,%3};"
        : "+f"(c0), "+f"(c1), "+f"(c2), "+f"(c3)
        : "r"(a0), "r"(a1), "r"(a2), "r"(a3), "r"(b0), "r"(b1));
}

__device__ __forceinline__ float sigmoidf_(float x) {
    return 1.0f / (1.0f + __expf(-x));
}

// k-within-16 permutation: lane tg's fragment ks {tg, tg+4, tg+8, tg+12} become
// contiguous floats -> one LDG/LDS .128 per two k-octets.
__device__ __forceinline__ int kperm(int k) {
    return (k & ~15) | ((k & 3) * 4 + ((k >> 2) & 3));
}

// ---------------- weight / bias packing ------------------------------------------
__global__ void pack_w(const float* __restrict__ Wi, const float* __restrict__ Wf,
                       const float* __restrict__ Wg, const float* __restrict__ Wo,
                       float* __restrict__ dst, int K) {
    int idx = blockIdx.x * blockDim.x + threadIdx.x;
    if (idx >= K * HDIM) return;
    float4 v;
    v.x = __uint_as_float(f2tf(Wi[idx]));
    v.y = __uint_as_float(f2tf(Wf[idx]));
    v.z = __uint_as_float(f2tf(Wg[idx]));
    v.w = __uint_as_float(f2tf(Wo[idx]));
    reinterpret_cast<float4*>(dst)[idx] = v;
}

__global__ void pack_b(const float* __restrict__ bi, const float* __restrict__ bf,
                       const float* __restrict__ bg, const float* __restrict__ bo,
                       float* __restrict__ dst) {
    int j = blockIdx.x * blockDim.x + threadIdx.x;
    if (j >= HDIM) return;
    float4 v;
    v.x = bi[j]; v.y = bf[j]; v.z = bg[j]; v.w = bo[j];
    reinterpret_cast<float4*>(dst)[j] = v;
}

// ---------------- big input-projection GEMM --------------------------------------
#define XBM 128
#define XBN 128
#define XBK 32

__global__ void __launch_bounds__(256)
gemm_xw(const float* __restrict__ A, const float* __restrict__ Bp,
        float* __restrict__ C, const float* __restrict__ bias) {
    __shared__ float As[XBM][XBK + 1];
    __shared__ float Bs[XBK][XBN + 4];

    const int m0 = blockIdx.y * XBM;
    const int n0 = blockIdx.x * XBN;
    const int tid  = threadIdx.x;
    const int warp = tid >> 5, lane = tid & 31;
    const int grp  = lane >> 2, tg = lane & 3;
    const int wm = warp & 3;
    const int wn = warp >> 2;

    float acc[2][8][4];
#pragma unroll
    for (int mt = 0; mt < 2; mt++)
#pragma unroll
        for (int nt = 0; nt < 8; nt++)
#pragma unroll
            for (int q = 0; q < 4; q++) acc[mt][nt][q] = 0.0f;

    for (int kb = 0; kb < KD; kb += XBK) {
#pragma unroll
        for (int it = 0; it < 4; it++) {
            int v = tid + it * 256;
            int r = v >> 3, c4 = (v & 7) << 2;
            float4 f = *reinterpret_cast<const float4*>(A + (size_t)(m0 + r) * KD + kb + c4);
            As[r][c4 + 0] = __uint_as_float(f2tf(f.x));
            As[r][c4 + 1] = __uint_as_float(f2tf(f.y));
            As[r][c4 + 2] = __uint_as_float(f2tf(f.z));
            As[r][c4 + 3] = __uint_as_float(f2tf(f.w));
        }
#pragma unroll
        for (int it = 0; it < 4; it++) {
            int v = tid + it * 256;
            int r = v >> 5, c4 = (v & 31) << 2;
            float4 f = *reinterpret_cast<const float4*>(Bp + (size_t)(kb + r) * G4 + n0 + c4);
            Bs[r][c4 + 0] = f.x;
            Bs[r][c4 + 1] = f.y;
            Bs[r][c4 + 2] = f.z;
            Bs[r][c4 + 3] = f.w;
        }
        __syncthreads();

#pragma unroll
        for (int kk = 0; kk < 4; kk++) {
            const int ks = kk * 8;
            unsigned a[2][4], b[8][2];
#pragma unroll
            for (int mt = 0; mt < 2; mt++) {
                int r = wm * 32 + mt * 16 + grp;
                a[mt][0] = __float_as_uint(As[r    ][ks + tg    ]);
                a[mt][1] = __float_as_uint(As[r + 8][ks + tg    ]);
                a[mt][2] = __float_as_uint(As[r    ][ks + tg + 4]);
                a[mt][3] = __float_as_uint(As[r + 8][ks + tg + 4]);
            }
#pragma unroll
            for (int nt = 0; nt < 8; nt++) {
                int c = wn * 64 + nt * 8 + grp;
                b[nt][0] = __float_as_uint(Bs[ks + tg    ][c]);
                b[nt][1] = __float_as_uint(Bs[ks + tg + 4][c]);
            }
#pragma unroll
            for (int mt = 0; mt < 2; mt++)
#pragma unroll
                for (int nt = 0; nt < 8; nt++)
                    mma_tf32(acc[mt][nt][0], acc[mt][nt][1], acc[mt][nt][2], acc[mt][nt][3],
                             a[mt][0], a[mt][1], a[mt][2], a[mt][3],
                             b[nt][0], b[nt][1]);
        }
        __syncthreads();
    }

#pragma unroll
    for (int mt = 0; mt < 2; mt++) {
        int r = m0 + wm * 32 + mt * 16 + grp;
#pragma unroll
        for (int nt = 0; nt < 8; nt++) {
            int c = n0 + wn * 64 + nt * 8 + tg * 2;
            float2 bv = *reinterpret_cast<const float2*>(bias + c);
            float2 o0, o1;
            o0.x = acc[mt][nt][0] + bv.x;  o0.y = acc[mt][nt][1] + bv.y;
            o1.x = acc[mt][nt][2] + bv.x;  o1.y = acc[mt][nt][3] + bv.y;
            *reinterpret_cast<float2*>(C + (size_t)r * G4 + c)       = o0;
            *reinterpret_cast<float2*>(C + (size_t)(r + 8) * G4 + c) = o1;
        }
    }
}

// ---------------- persistent recurrent layer -------------------------------------
// 128 CTAs x 256 threads (8 warps = 2 M-halves x 4 K-slices), 1 CTA/SM.
// Each CTA owns 32 packed gate columns (8 hidden units). W_h slice persists in
// SMEM (k-permuted, transposed). A fragments come straight from GLOBAL h
// (k-permuted ping-pong buffers) as LDG.128 — no SMEM staging, no per-chunk
// syncthreads. K-split partials reduced in the pointwise epilogue.
#define WT_STRIDE 1040              // == 16 mod 32 -> conflict-free LDS.128
#define PS_STRIDE 36
#define SMEM_FLOATS (32 * WT_STRIDE + 4 * 64 * PS_STRIDE)

__device__ __forceinline__ void grid_bar(unsigned& sense) {
    __syncthreads();
    sense ^= 1u;
    if (threadIdx.x == 0) {
        __threadfence();
        if (atomicAdd(&g_bcount, 1u) == NCTA - 1) {
            g_bcount = 0;
            __threadfence();
            g_bsense = sense;
        } else {
            while (g_bsense != sense) { __nanosleep(32); }
        }
        __threadfence();
    }
    __syncthreads();
}

__global__ void __launch_bounds__(NTHR, 1)
lstm_layer(const float* __restrict__ xw, float* __restrict__ h0,
           float* __restrict__ h1, float* __restrict__ cdump,
           float* __restrict__ seq_out) {
    extern __shared__ float smem[];
    float* Wt = smem;                        // [32][WT_STRIDE]  Wt[col][kperm]
    float* Ps = Wt + 32 * WT_STRIDE;         // [4][64][PS_STRIDE] k-split partials

    const int tid  = threadIdx.x;
    const int warp = tid >> 5, lane = tid & 31;
    const int grp  = lane >> 2, tg = lane & 3;
    const int wm = warp & 1;                 // M half: rows wm*32..+31
    const int ks = warp >> 1;                // K slice: k in [ks*256, ks*256+256)

    const int n0 = blockIdx.x * 32;          // packed gate column base
    const int J0 = blockIdx.x * 8;           // hidden-unit base

    // ---- preload W_h slice into SMEM: Wt[c][kperm(k)] = Wh[k][n0+c] ----
    for (int idx = tid; idx < 32 * 1024; idx += NTHR) {
        int c = idx & 31, k = idx >> 5;
        Wt[c * WT_STRIDE + kperm(k)] = g_Wh[(size_t)k * G4 + n0 + c];
    }

    // ---- zero h (own columns, both buffers; zeros are perm-invariant) ----
    for (int idx = tid; idx < 512; idx += NTHR) {
        int b = idx >> 3, j = idx & 7;
        h0[b * HDIM + J0 + j] = 0.0f;
        h1[b * HDIM + J0 + j] = 0.0f;
    }

    unsigned sense = 0;
    grid_bar(sense);                         // barrier #1 (init)

    float creg[2] = {0.0f, 0.0f};
    float* hbuf[2] = {h0, h1};

    // row bases for this warp's A fragments (4 rows/lane: grp, +8, +16, +24)
    const int r0 = wm * 32 + grp;
    const int kbase = ks * 256;

    for (int s = 0; s < SEQ; s++) {
        const float* __restrict__ hr = hbuf[s & 1];
        float* __restrict__ hw = hbuf[(s + 1) & 1];

        float acc[2][4][4];
#pragma unroll
        for (int mt = 0; mt < 2; mt++)
#pragma unroll
            for (int nt = 0; nt < 4; nt++)
#pragma unroll
                for (int q = 0; q < 4; q++) acc[mt][nt][q] = 0.0f;

        const float* hA0 = hr + (size_t)(r0     ) * KD + kbase + tg * 4;
        const float* hA1 = hr + (size_t)(r0 +  8) * KD + kbase + tg * 4;
        const float* hA2 = hr + (size_t)(r0 + 16) * KD + kbase + tg * 4;
        const float* hA3 = hr + (size_t)(r0 + 24) * KD + kbase + tg * 4;

        // prologue: group 0
        float4 A0 = *reinterpret_cast<const float4*>(hA0);
        float4 A1 = *reinterpret_cast<const float4*>(hA1);
        float4 A2 = *reinterpret_cast<const float4*>(hA2);
        float4 A3 = *reinterpret_cast<const float4*>(hA3);

#pragma unroll
        for (int g = 0; g < 16; g++) {
            float4 P0, P1, P2, P3;
            if (g < 15) {
                const int off = (g + 1) * 16;
                P0 = *reinterpret_cast<const float4*>(hA0 + off);
                P1 = *reinterpret_cast<const float4*>(hA1 + off);
                P2 = *reinterpret_cast<const float4*>(hA2 + off);
                P3 = *reinterpret_cast<const float4*>(hA3 + off);
            }

            // B fragments: 4 n8 tiles, one LDS.128 each (covers both k-octets)
            float4 Bv[4];
#pragma unroll
            for (int nt = 0; nt < 4; nt++) {
                const int c = nt * 8 + grp;
                Bv[nt] = *reinterpret_cast<const float4*>(
                    Wt + c * WT_STRIDE + kbase + g * 16 + tg * 4);
            }

            // octet 0: logical k = {tg, tg+4}  (components .x, .y)
#pragma unroll
            for (int nt = 0; nt < 4; nt++) {
                mma_tf32(acc[0][nt][0], acc[0][nt][1], acc[0][nt][2], acc[0][nt][3],
                         __float_as_uint(A0.x), __float_as_uint(A1.x),
                         __float_as_uint(A0.y), __float_as_uint(A1.y),
                         __float_as_uint(Bv[nt].x), __float_as_uint(Bv[nt].y));
                mma_tf32(acc[1][nt][0], acc[1][nt][1], acc[1][nt][2], acc[1][nt][3],
                         __float_as_uint(A2.x), __float_as_uint(A3.x),
                         __float_as_uint(A2.y), __float_as_uint(A3.y),
                         __float_as_uint(Bv[nt].x), __float_as_uint(Bv[nt].y));
            }
            // octet 1: logical k = {tg+8, tg+12} (components .z, .w)
#pragma unroll
            for (int nt = 0; nt < 4; nt++) {
                mma_tf32(acc[0][nt][0], acc[0][nt][1], acc[0][nt][2], acc[0][nt][3],
                         __float_as_uint(A0.z), __float_as_uint(A1.z),
                         __float_as_uint(A0.w), __float_as_uint(A1.w),
                         __float_as_uint(Bv[nt].z), __float_as_uint(Bv[nt].w));
                mma_tf32(acc[1][nt][0], acc[1][nt][1], acc[1][nt][2], acc[1][nt][3],
                         __float_as_uint(A2.z), __float_as_uint(A3.z),
                         __float_as_uint(A2.w), __float_as_uint(A3.w),
                         __float_as_uint(Bv[nt].z), __float_as_uint(Bv[nt].w));
            }

            A0 = P0; A1 = P1; A2 = P2; A3 = P3;
        }

        // spill k-split partials: Ps[ks][row][col]
        {
            float* P = Ps + ks * 64 * PS_STRIDE;
#pragma unroll
            for (int mt = 0; mt < 2; mt++) {
                const int r = wm * 32 + mt * 16 + grp;
#pragma unroll
                for (int nt = 0; nt < 4; nt++) {
                    const int c = nt * 8 + tg * 2;
                    *reinterpret_cast<float2*>(P + (r    ) * PS_STRIDE + c) =
                        make_float2(acc[mt][nt][0], acc[mt][nt][1]);
                    *reinterpret_cast<float2*>(P + (r + 8) * PS_STRIDE + c) =
                        make_float2(acc[mt][nt][2], acc[mt][nt][3]);
                }
            }
        }
        __syncthreads();

        // pointwise LSTM update + k-split reduction (2 items/thread)
        const float* xw_t = xw + (size_t)s * BS * G4;
        float* so = seq_out + (size_t)s * BS * HDIM;
#pragma unroll
        for (int it = 0; it < 2; it++) {
            int idx = tid + it * NTHR;       // 0..511
            int b = idx >> 3, j = idx & 7;
            int col = j << 2;
            float4 xv = *reinterpret_cast<const float4*>(xw_t + (size_t)b * G4 + n0 + col);
            float4 p0 = *reinterpret_cast<const float4*>(Ps + 0 * 64 * PS_STRIDE + b * PS_STRIDE + col);
            float4 p1 = *reinterpret_cast<const float4*>(Ps + 1 * 64 * PS_STRIDE + b * PS_STRIDE + col);
            float4 p2 = *reinterpret_cast<const float4*>(Ps + 2 * 64 * PS_STRIDE + b * PS_STRIDE + col);
            float4 p3 = *reinterpret_cast<const float4*>(Ps + 3 * 64 * PS_STRIDE + b * PS_STRIDE + col);

            float pi  = xv.x + ((p0.x + p1.x) + (p2.x + p3.x));
            float pfv = xv.y + ((p0.y + p1.y) + (p2.y + p3.y));
            float pg  = xv.z + ((p0.z + p1.z) + (p2.z + p3.z));
            float po  = xv.w + ((p0.w + p1.w) + (p2.w + p3.w));

            float gi = sigmoidf_(pi);
            float gf = sigmoidf_(pfv);
            float gg = tanhf(pg);
            float go = sigmoidf_(po);

            float cv = gf * creg[it] + gi * gg;
            creg[it] = cv;
            float hv = go * tanhf(cv);

            int J = J0 + j;
            hw[b * HDIM + kperm(J)] = __uint_as_float(f2tf(hv)); // permuted, tf32
            so[b * HDIM + J] = hv;                               // full precision
            if (s == SEQ - 1) cdump[b * HDIM + J] = cv;
        }

        if (s < SEQ - 1) grid_bar(sense);    // barriers #2..#512 (total even)
    }
}

// ---------------- tail: (h, c) after the sequence --------------------------------
__global__ void copy_tail(const float* __restrict__ hsrc, const float* __restrict__ csrc,
                          float* __restrict__ dst) {
    int i = blockIdx.x * blockDim.x + threadIdx.x;
    if (i < BS * HDIM) {
        dst[i] = hsrc[i];
        dst[BS * HDIM + i] = csrc[i];
    }
}

// ---------------- launcher --------------------------------------------------------
extern "C" void kernel_launch(void* const* d_in, const int* in_sizes, int n_in,
                              void* d_out, int out_size) {
    (void)in_sizes; (void)n_in;

    const float* x     = (const float*)d_in[0];
    const float* Wii0  = (const float*)d_in[1];
    const float* Wii   = (const float*)d_in[2];
    const float* Whi   = (const float*)d_in[3];
    const float* Wif0  = (const float*)d_in[4];
    const float* Wif   = (const float*)d_in[5];
    const float* Whf   = (const float*)d_in[6];
    const float* Wig0  = (const float*)d_in[7];
    const float* Wig   = (const float*)d_in[8];
    const float* Whg   = (const float*)d_in[9];
    const float* Wio0  = (const float*)d_in[10];
    const float* Wio   = (const float*)d_in[11];
    const float* Who   = (const float*)d_in[12];
    const float* bi    = (const float*)d_in[13];
    const float* bf    = (const float*)d_in[14];
    const float* bg    = (const float*)d_in[15];
    const float* bo    = (const float*)d_in[16];

    float *pWx0, *pWx1, *pWh, *pBias, *pXw, *pSeq0, *pHA, *pHB, *pC;
    cudaGetSymbolAddress((void**)&pWx0,  g_Wx0);
    cudaGetSymbolAddress((void**)&pWx1,  g_Wx1);
    cudaGetSymbolAddress((void**)&pWh,   g_Wh);
    cudaGetSymbolAddress((void**)&pBias, g_bias);
    cudaGetSymbolAddress((void**)&pXw,   g_xw);
    cudaGetSymbolAddress((void**)&pSeq0, g_seq0);
    cudaGetSymbolAddress((void**)&pHA,   g_hA);
    cudaGetSymbolAddress((void**)&pHB,   g_hB);
    cudaGetSymbolAddress((void**)&pC,    g_c);

    float* out = (float*)d_out;

    static bool attr_set = false;
    if (!attr_set) {
        cudaFuncSetAttribute(lstm_layer, cudaFuncAttributeMaxDynamicSharedMemorySize,
                             SMEM_FLOATS * (int)sizeof(float));
        attr_set = true;
    }

    // pack weights / bias
    {
        int n = IN_DIM * HDIM;
        pack_w<<<(n + 255) / 256, 256>>>(Wii0, Wif0, Wig0, Wio0, pWx0, IN_DIM);
        n = HDIM * HDIM;
        pack_w<<<(n + 255) / 256, 256>>>(Wii,  Wif,  Wig,  Wio,  pWx1, HDIM);
        pack_w<<<(n + 255) / 256, 256>>>(Whi,  Whf,  Whg,  Who,  pWh,  HDIM);
        pack_b<<<(HDIM + 255) / 256, 256>>>(bi, bf, bg, bo, pBias);
    }

    const dim3 gemm_grid(G4 / XBN, (SEQ * BS) / XBM);  // (32, 256)
    const size_t smem_bytes = SMEM_FLOATS * sizeof(float);

    // ---------------- layer 0 ----------------
    gemm_xw<<<gemm_grid, 256>>>(x, pWx0, pXw, pBias);
    lstm_layer<<<NCTA, NTHR, smem_bytes>>>(pXw, pHA, pHB, pC, pSeq0);

    // ---------------- layer 1 ----------------
    gemm_xw<<<gemm_grid, 256>>>(pSeq0, pWx1, pXw, pBias);
    lstm_layer<<<NCTA, NTHR, smem_bytes>>>(pXw, pHA, pHB, pC, out);

    // tail: final (h, c). h final = seq output at t = SEQ-1 (full precision).
    size_t seqN = (size_t)SEQ * BS * HDIM;
    if ((size_t)out_size >= seqN + 2 * (size_t)BS * HDIM) {
        copy_tail<<<(BS * HDIM + 255) / 256, 256>>>(out + seqN - (size_t)BS * HDIM,
                                                    pC, out + seqN);
    }
}

// round 4
// speedup vs baseline: 1.8873x; 1.3068x over previous
#include <cuda_runtime.h>
#include <cuda_fp16.h>
#include <cstdint>

#define SEQ 512
#define BS 64
#define IN_DIM 1024
#define HDIM 1024
#define G4 4096           // 4 gates * H, packed as [k][j*4 + gate]
#define KD 1024
#define NCTA 128
#define NTHR 256

// ---------------- device scratch (allocation rules forbid cudaMalloc) -----------
__device__ float g_Wx0[IN_DIM * G4];
__device__ float g_Wx1[HDIM * G4];
__device__ float g_Wh [HDIM * G4];
__device__ float g_bias[G4];
__device__ float g_xw [(size_t)SEQ * BS * G4];    // X@W + b for current layer
__device__ float g_seq0[(size_t)SEQ * BS * HDIM]; // layer0 output sequence
__device__ __half g_hA[BS * HDIM];                // h ping-pong (fp16, k-PERMUTED)
__device__ __half g_hB[BS * HDIM];
__device__ float g_c [BS * HDIM];

// monotonic per-CTA step flags (graph-replay safe: base re-read each launch)
__device__ unsigned g_flags[NCTA];

// ---------------- helpers -------------------------------------------------------
__device__ __forceinline__ unsigned f2tf(float x) {
    unsigned u;
    asm("cvt.rna.tf32.f32 %0, %1;" : "=r"(u) : "f"(x));
    return u;
}

__device__ __forceinline__ void mma_tf32(float& c0, float& c1, float& c2, float& c3,
                                         unsigned a0, unsigned a1, unsigned a2, unsigned a3,
                                         unsigned b0, unsigned b1) {
    asm volatile(
        "mma.sync.aligned.m16n8k8.row.col.f32.tf32.tf32.f32 "
        "{%0,%1,%2,%3}, {%4,%5,%6,%7}, {%8,%9}, {%0,%1,%2,%3};"
        : "+f"(c0), "+f"(c1), "+f"(c2), "+f"(c3)
        : "r"(a0), "r"(a1), "r"(a2), "r"(a3), "r"(b0), "r"(b1));
}

__device__ __forceinline__ void mma_f16(float& c0, float& c1, float& c2, float& c3,
                                        unsigned a0, unsigned a1, unsigned a2, unsigned a3,
                                        unsigned b0, unsigned b1) {
    asm volatile(
        "mma.sync.aligned.m16n8k16.row.col.f32.f16.f16.f32 "
        "{%0,%1,%2,%3}, {%4,%5,%6,%7}, {%8,%9}, {%0,%1,%2,%3};"
        : "+f"(c0), "+f"(c1), "+f"(c2), "+f"(c3)
        : "r"(a0), "r"(a1), "r"(a2), "r"(a3), "r"(b0), "r"(b1));
}

__device__ __forceinline__ float sigmoidf_(float x) {
    return 1.0f / (1.0f + __expf(-x));
}

__device__ __forceinline__ unsigned ld_acq(const unsigned* p) {
    unsigned v;
    asm volatile("ld.acquire.gpu.global.u32 %0, [%1];" : "=r"(v) : "l"(p) : "memory");
    return v;
}
__device__ __forceinline__ void st_rel(unsigned* p, unsigned v) {
    asm volatile("st.release.gpu.global.u32 [%0], %1;" :: "l"(p), "r"(v) : "memory");
}

// fp16 k-permutation within each 32-k block: lane tg's 8 halves for two k16
// MMA tiles become one contiguous 16B vector.
// pos = tg*8 + tile*4 + c*2 + b  where k%32 = tile*16 + c*8 + 2*tg + b
__device__ __forceinline__ int hperm16(int k) {
    int t = k & 31;
    int tile = t >> 4;
    int u = t & 15;
    int b = u & 1;
    int tg = (u >> 1) & 3;
    int c = u >> 3;
    return (k & ~31) | (tg * 8 + tile * 4 + c * 2 + b);
}

// ---------------- weight / bias packing ------------------------------------------
__global__ void pack_w(const float* __restrict__ Wi, const float* __restrict__ Wf,
                       const float* __restrict__ Wg, const float* __restrict__ Wo,
                       float* __restrict__ dst, int K) {
    int idx = blockIdx.x * blockDim.x + threadIdx.x;
    if (idx >= K * HDIM) return;
    float4 v;
    v.x = __uint_as_float(f2tf(Wi[idx]));
    v.y = __uint_as_float(f2tf(Wf[idx]));
    v.z = __uint_as_float(f2tf(Wg[idx]));
    v.w = __uint_as_float(f2tf(Wo[idx]));
    reinterpret_cast<float4*>(dst)[idx] = v;
}

__global__ void pack_b(const float* __restrict__ bi, const float* __restrict__ bf,
                       const float* __restrict__ bg, const float* __restrict__ bo,
                       float* __restrict__ dst) {
    int j = blockIdx.x * blockDim.x + threadIdx.x;
    if (j >= HDIM) return;
    float4 v;
    v.x = bi[j]; v.y = bf[j]; v.z = bg[j]; v.w = bo[j];
    reinterpret_cast<float4*>(dst)[j] = v;
}

// ---------------- big input-projection GEMM (tf32, unchanged) --------------------
#define XBM 128
#define XBN 128
#define XBK 32

__global__ void __launch_bounds__(256)
gemm_xw(const float* __restrict__ A, const float* __restrict__ Bp,
        float* __restrict__ C, const float* __restrict__ bias) {
    __shared__ float As[XBM][XBK + 1];
    __shared__ float Bs[XBK][XBN + 4];

    const int m0 = blockIdx.y * XBM;
    const int n0 = blockIdx.x * XBN;
    const int tid  = threadIdx.x;
    const int warp = tid >> 5, lane = tid & 31;
    const int grp  = lane >> 2, tg = lane & 3;
    const int wm = warp & 3;
    const int wn = warp >> 2;

    float acc[2][8][4];
#pragma unroll
    for (int mt = 0; mt < 2; mt++)
#pragma unroll
        for (int nt = 0; nt < 8; nt++)
#pragma unroll
            for (int q = 0; q < 4; q++) acc[mt][nt][q] = 0.0f;

    for (int kb = 0; kb < KD; kb += XBK) {
#pragma unroll
        for (int it = 0; it < 4; it++) {
            int v = tid + it * 256;
            int r = v >> 3, c4 = (v & 7) << 2;
            float4 f = *reinterpret_cast<const float4*>(A + (size_t)(m0 + r) * KD + kb + c4);
            As[r][c4 + 0] = __uint_as_float(f2tf(f.x));
            As[r][c4 + 1] = __uint_as_float(f2tf(f.y));
            As[r][c4 + 2] = __uint_as_float(f2tf(f.z));
            As[r][c4 + 3] = __uint_as_float(f2tf(f.w));
        }
#pragma unroll
        for (int it = 0; it < 4; it++) {
            int v = tid + it * 256;
            int r = v >> 5, c4 = (v & 31) << 2;
            float4 f = *reinterpret_cast<const float4*>(Bp + (size_t)(kb + r) * G4 + n0 + c4);
            Bs[r][c4 + 0] = f.x;
            Bs[r][c4 + 1] = f.y;
            Bs[r][c4 + 2] = f.z;
            Bs[r][c4 + 3] = f.w;
        }
        __syncthreads();

#pragma unroll
        for (int kk = 0; kk < 4; kk++) {
            const int ks = kk * 8;
            unsigned a[2][4], b[8][2];
#pragma unroll
            for (int mt = 0; mt < 2; mt++) {
                int r = wm * 32 + mt * 16 + grp;
                a[mt][0] = __float_as_uint(As[r    ][ks + tg    ]);
                a[mt][1] = __float_as_uint(As[r + 8][ks + tg    ]);
                a[mt][2] = __float_as_uint(As[r    ][ks + tg + 4]);
                a[mt][3] = __float_as_uint(As[r + 8][ks + tg + 4]);
            }
#pragma unroll
            for (int nt = 0; nt < 8; nt++) {
                int c = wn * 64 + nt * 8 + grp;
                b[nt][0] = __float_as_uint(Bs[ks + tg    ][c]);
                b[nt][1] = __float_as_uint(Bs[ks + tg + 4][c]);
            }
#pragma unroll
            for (int mt = 0; mt < 2; mt++)
#pragma unroll
                for (int nt = 0; nt < 8; nt++)
                    mma_tf32(acc[mt][nt][0], acc[mt][nt][1], acc[mt][nt][2], acc[mt][nt][3],
                             a[mt][0], a[mt][1], a[mt][2], a[mt][3],
                             b[nt][0], b[nt][1]);
        }
        __syncthreads();
    }

#pragma unroll
    for (int mt = 0; mt < 2; mt++) {
        int r = m0 + wm * 32 + mt * 16 + grp;
#pragma unroll
        for (int nt = 0; nt < 8; nt++) {
            int c = n0 + wn * 64 + nt * 8 + tg * 2;
            float2 bv = *reinterpret_cast<const float2*>(bias + c);
            float2 o0, o1;
            o0.x = acc[mt][nt][0] + bv.x;  o0.y = acc[mt][nt][1] + bv.y;
            o1.x = acc[mt][nt][2] + bv.x;  o1.y = acc[mt][nt][3] + bv.y;
            *reinterpret_cast<float2*>(C + (size_t)r * G4 + c)       = o0;
            *reinterpret_cast<float2*>(C + (size_t)(r + 8) * G4 + c) = o1;
        }
    }
}

// ---------------- persistent recurrent layer (fp16 MMA) ---------------------------
// 128 CTAs x 256 threads (8 warps = 2 M-halves x 4 K-slices), 1 CTA/SM.
// W_h slice persists in SMEM as fp16 (k-permuted, transposed). A fragments are
// LDG.128 straight from the permuted fp16 global h ping-pong. Flag-array grid
// barrier (no atomics). K-split partials (fp32) reduced in pointwise epilogue.
#define WT_STRIDE 1056              // halves; 8*2*1056 % 128 == 64 -> conflict-free
#define PS_STRIDE 36
#define SMEM_BYTES (32 * WT_STRIDE * 2 + 4 * 64 * PS_STRIDE * 4)

__global__ void __launch_bounds__(NTHR, 1)
lstm_layer(const float* __restrict__ xw, __half* __restrict__ h0,
           __half* __restrict__ h1, float* __restrict__ cdump,
           float* __restrict__ seq_out) {
    extern __shared__ __align__(16) unsigned char smem_raw[];
    __half* Wt = reinterpret_cast<__half*>(smem_raw);              // [32][WT_STRIDE]
    float*  Ps = reinterpret_cast<float*>(smem_raw + 32 * WT_STRIDE * 2); // [4][64][36]

    const int tid  = threadIdx.x;
    const int warp = tid >> 5, lane = tid & 31;
    const int grp  = lane >> 2, tg = lane & 3;
    const int wm = warp & 1;                 // M half: rows wm*32..+31
    const int ks = warp >> 1;                // K slice: [ks*256, ks*256+256)

    const int n0 = blockIdx.x * 32;          // packed gate column base
    const int J0 = blockIdx.x * 8;           // hidden-unit base

    // base flag value (uniform across CTAs at launch start)
    const unsigned base = g_flags[blockIdx.x];

    // ---- preload W_h slice into SMEM: Wt[c][hperm16(k)] = half(Wh[k][n0+c]) ----
    for (int idx = tid; idx < 32 * 1024; idx += NTHR) {
        int c = idx & 31, k = idx >> 5;
        Wt[c * WT_STRIDE + hperm16(k)] = __float2half(g_Wh[(size_t)k * G4 + n0 + c]);
    }

    // ---- zero own h columns (both buffers; zero is perm-trivial but use perm) ----
    for (int idx = tid; idx < 512; idx += NTHR) {
        int b = idx >> 3, j = idx & 7;
        int p = b * HDIM + hperm16(J0 + j);
        h0[p] = __float2half(0.0f);
        h1[p] = __float2half(0.0f);
    }

    // arrive: h for step 0 ready
    __syncthreads();
    if (tid == 0) st_rel(&g_flags[blockIdx.x], base + 1);

    float creg[2] = {0.0f, 0.0f};
    __half* hbuf[2] = {h0, h1};

    const int r0 = wm * 32 + grp;            // lane's base row
    const int kbase = ks * 256;              // lane's k-slice base

    for (int s = 0; s < SEQ; s++) {
        const __half* __restrict__ hr = hbuf[s & 1];
        __half* __restrict__ hw = hbuf[(s + 1) & 1];

        // ---- prefetch xw_t (independent of h) before the wait ----
        const float* xw_t = xw + (size_t)s * BS * G4;
        float4 xv[2];
#pragma unroll
        for (int it = 0; it < 2; it++) {
            int idx = tid + it * NTHR;
            int b = idx >> 3, col = (idx & 7) << 2;
            xv[it] = *reinterpret_cast<const float4*>(xw_t + (size_t)b * G4 + n0 + col);
        }

        // ---- wait: all CTAs' h writes for step s visible ----
        {
            const unsigned target = base + 1 + (unsigned)s;
            bool ok;
            do {
                unsigned v = (tid < NCTA) ? ld_acq(&g_flags[tid]) : target;
                ok = (int)(v - target) >= 0;
            } while (!__syncthreads_and(ok));
        }

        float acc[2][4][4];
#pragma unroll
        for (int mt = 0; mt < 2; mt++)
#pragma unroll
            for (int nt = 0; nt < 4; nt++)
#pragma unroll
                for (int q = 0; q < 4; q++) acc[mt][nt][q] = 0.0f;

        // lane A pointers: 4 rows (r0, +8, +16, +24), 16B per 32-k block
        const __half* hA0 = hr + (size_t)(r0     ) * KD + kbase + tg * 8;
        const __half* hA1 = hr + (size_t)(r0 +  8) * KD + kbase + tg * 8;
        const __half* hA2 = hr + (size_t)(r0 + 16) * KD + kbase + tg * 8;
        const __half* hA3 = hr + (size_t)(r0 + 24) * KD + kbase + tg * 8;

        uint4 A0 = *reinterpret_cast<const uint4*>(hA0);
        uint4 A1 = *reinterpret_cast<const uint4*>(hA1);
        uint4 A2 = *reinterpret_cast<const uint4*>(hA2);
        uint4 A3 = *reinterpret_cast<const uint4*>(hA3);

#pragma unroll
        for (int g = 0; g < 8; g++) {        // 8 x 32-k blocks = 256 k
            uint4 P0, P1, P2, P3;
            if (g < 7) {
                const int off = (g + 1) * 32;
                P0 = *reinterpret_cast<const uint4*>(hA0 + off);
                P1 = *reinterpret_cast<const uint4*>(hA1 + off);
                P2 = *reinterpret_cast<const uint4*>(hA2 + off);
                P3 = *reinterpret_cast<const uint4*>(hA3 + off);
            }

            // B fragments: 4 n8 tiles, one LDS.128 each covers two k16 tiles
            uint4 Bv[4];
#pragma unroll
            for (int nt = 0; nt < 4; nt++) {
                const int c = nt * 8 + grp;
                Bv[nt] = *reinterpret_cast<const uint4*>(
                    Wt + c * WT_STRIDE + kbase + g * 32 + tg * 8);
            }

            // k16 tile 0 (components .x [k0..1], .y [k8..9])
#pragma unroll
            for (int nt = 0; nt < 4; nt++) {
                mma_f16(acc[0][nt][0], acc[0][nt][1], acc[0][nt][2], acc[0][nt][3],
                        A0.x, A1.x, A0.y, A1.y, Bv[nt].x, Bv[nt].y);
                mma_f16(acc[1][nt][0], acc[1][nt][1], acc[1][nt][2], acc[1][nt][3],
                        A2.x, A3.x, A2.y, A3.y, Bv[nt].x, Bv[nt].y);
            }
            // k16 tile 1 (components .z, .w)
#pragma unroll
            for (int nt = 0; nt < 4; nt++) {
                mma_f16(acc[0][nt][0], acc[0][nt][1], acc[0][nt][2], acc[0][nt][3],
                        A0.z, A1.z, A0.w, A1.w, Bv[nt].z, Bv[nt].w);
                mma_f16(acc[1][nt][0], acc[1][nt][1], acc[1][nt][2], acc[1][nt][3],
                        A2.z, A3.z, A2.w, A3.w, Bv[nt].z, Bv[nt].w);
            }

            A0 = P0; A1 = P1; A2 = P2; A3 = P3;
        }

        // spill k-split partials: Ps[ks][row][col]
        {
            float* P = Ps + ks * 64 * PS_STRIDE;
#pragma unroll
            for (int mt = 0; mt < 2; mt++) {
                const int r = wm * 32 + mt * 16 + grp;
#pragma unroll
                for (int nt = 0; nt < 4; nt++) {
                    const int c = nt * 8 + tg * 2;
                    *reinterpret_cast<float2*>(P + (r    ) * PS_STRIDE + c) =
                        make_float2(acc[mt][nt][0], acc[mt][nt][1]);
                    *reinterpret_cast<float2*>(P + (r + 8) * PS_STRIDE + c) =
                        make_float2(acc[mt][nt][2], acc[mt][nt][3]);
                }
            }
        }
        __syncthreads();

        // pointwise LSTM update + k-split reduction (2 items/thread)
        float* so = seq_out + (size_t)s * BS * HDIM;
#pragma unroll
        for (int it = 0; it < 2; it++) {
            int idx = tid + it * NTHR;       // 0..511
            int b = idx >> 3, j = idx & 7;
            int col = j << 2;
            float4 p0 = *reinterpret_cast<const float4*>(Ps + 0 * 64 * PS_STRIDE + b * PS_STRIDE + col);
            float4 p1 = *reinterpret_cast<const float4*>(Ps + 1 * 64 * PS_STRIDE + b * PS_STRIDE + col);
            float4 p2 = *reinterpret_cast<const float4*>(Ps + 2 * 64 * PS_STRIDE + b * PS_STRIDE + col);
            float4 p3 = *reinterpret_cast<const float4*>(Ps + 3 * 64 * PS_STRIDE + b * PS_STRIDE + col);

            float pi  = xv[it].x + ((p0.x + p1.x) + (p2.x + p3.x));
            float pfv = xv[it].y + ((p0.y + p1.y) + (p2.y + p3.y));
            float pg  = xv[it].z + ((p0.z + p1.z) + (p2.z + p3.z));
            float po  = xv[it].w + ((p0.w + p1.w) + (p2.w + p3.w));

            float gi = sigmoidf_(pi);
            float gf = sigmoidf_(pfv);
            float gg = tanhf(pg);
            float go = sigmoidf_(po);

            float cv = gf * creg[it] + gi * gg;
            creg[it] = cv;
            float hv = go * tanhf(cv);

            int J = J0 + j;
            hw[b * HDIM + hperm16(J)] = __float2half(hv);  // fp16, permuted
            so[b * HDIM + J] = hv;                          // full precision
            if (s == SEQ - 1) cdump[b * HDIM + J] = cv;
        }

        // arrive: h for step s+1 ready (and our reads of step s are done)
        __syncthreads();
        if (tid == 0) st_rel(&g_flags[blockIdx.x], base + 2 + (unsigned)s);
    }
}

// ---------------- tail: (h, c) after the sequence --------------------------------
__global__ void copy_tail(const float* __restrict__ hsrc, const float* __restrict__ csrc,
                          float* __restrict__ dst) {
    int i = blockIdx.x * blockDim.x + threadIdx.x;
    if (i < BS * HDIM) {
        dst[i] = hsrc[i];
        dst[BS * HDIM + i] = csrc[i];
    }
}

// ---------------- launcher --------------------------------------------------------
extern "C" void kernel_launch(void* const* d_in, const int* in_sizes, int n_in,
                              void* d_out, int out_size) {
    (void)in_sizes; (void)n_in;

    const float* x     = (const float*)d_in[0];
    const float* Wii0  = (const float*)d_in[1];
    const float* Wii   = (const float*)d_in[2];
    const float* Whi   = (const float*)d_in[3];
    const float* Wif0  = (const float*)d_in[4];
    const float* Wif   = (const float*)d_in[5];
    const float* Whf   = (const float*)d_in[6];
    const float* Wig0  = (const float*)d_in[7];
    const float* Wig   = (const float*)d_in[8];
    const float* Whg   = (const float*)d_in[9];
    const float* Wio0  = (const float*)d_in[10];
    const float* Wio   = (const float*)d_in[11];
    const float* Who   = (const float*)d_in[12];
    const float* bi    = (const float*)d_in[13];
    const float* bf    = (const float*)d_in[14];
    const float* bg    = (const float*)d_in[15];
    const float* bo    = (const float*)d_in[16];

    float *pWx0, *pWx1, *pWh, *pBias, *pXw, *pSeq0, *pC;
    __half *pHA, *pHB;
    cudaGetSymbolAddress((void**)&pWx0,  g_Wx0);
    cudaGetSymbolAddress((void**)&pWx1,  g_Wx1);
    cudaGetSymbolAddress((void**)&pWh,   g_Wh);
    cudaGetSymbolAddress((void**)&pBias, g_bias);
    cudaGetSymbolAddress((void**)&pXw,   g_xw);
    cudaGetSymbolAddress((void**)&pSeq0, g_seq0);
    cudaGetSymbolAddress((void**)&pHA,   g_hA);
    cudaGetSymbolAddress((void**)&pHB,   g_hB);
    cudaGetSymbolAddress((void**)&pC,    g_c);

    float* out = (float*)d_out;

    static bool attr_set = false;
    if (!attr_set) {
        cudaFuncSetAttribute(lstm_layer, cudaFuncAttributeMaxDynamicSharedMemorySize,
                             SMEM_BYTES);
        attr_set = true;
    }

    // pack weights / bias
    {
        int n = IN_DIM * HDIM;
        pack_w<<<(n + 255) / 256, 256>>>(Wii0, Wif0, Wig0, Wio0, pWx0, IN_DIM);
        n = HDIM * HDIM;
        pack_w<<<(n + 255) / 256, 256>>>(Wii,  Wif,  Wig,  Wio,  pWx1, HDIM);
        pack_w<<<(n + 255) / 256, 256>>>(Whi,  Whf,  Whg,  Who,  pWh,  HDIM);
        pack_b<<<(HDIM + 255) / 256, 256>>>(bi, bf, bg, bo, pBias);
    }

    const dim3 gemm_grid(G4 / XBN, (SEQ * BS) / XBM);  // (32, 256)

    // ---------------- layer 0 ----------------
    gemm_xw<<<gemm_grid, 256>>>(x, pWx0, pXw, pBias);
    lstm_layer<<<NCTA, NTHR, SMEM_BYTES>>>(pXw, pHA, pHB, pC, pSeq0);

    // ---------------- layer 1 ----------------
    gemm_xw<<<gemm_grid, 256>>>(pSeq0, pWx1, pXw, pBias);
    lstm_layer<<<NCTA, NTHR, SMEM_BYTES>>>(pXw, pHA, pHB, pC, out);

    // tail: final (h, c). h final = seq output at t = SEQ-1 (full precision).
    size_t seqN = (size_t)SEQ * BS * HDIM;
    if ((size_t)out_size >= seqN + 2 * (size_t)BS * HDIM) {
        copy_tail<<<(BS * HDIM + 255) / 256, 256>>>(out + seqN - (size_t)BS * HDIM,
                                                    pC, out + seqN);
    }
}

// round 5
// speedup vs baseline: 1.9707x; 1.0442x over previous
#include <cuda_runtime.h>
#include <cuda_fp16.h>
#include <cstdint>

#define SEQ 512
#define BS 64
#define IN_DIM 1024
#define HDIM 1024
#define G4 4096           // 4 gates * H, packed as [k][j*4 + gate]
#define KD 1024
#define NCTA 128
#define NTHR 256

// ---------------- device scratch (allocation rules forbid cudaMalloc) -----------
__device__ __half g_Wx0h[(size_t)G4 * KD];        // layer0 input W, [n][kperm] fp16
__device__ __half g_Wx1h[(size_t)G4 * KD];        // layer>=1 input W, [n][kperm] fp16
__device__ float  g_Wh [HDIM * G4];               // recurrent W fp32 [k][n-packed]
__device__ float  g_bias[G4];
__device__ float  g_xw [(size_t)SEQ * BS * G4];   // X@W + b for current layer
__device__ __half g_Ah [(size_t)SEQ * BS * KD];   // GEMM A, fp16 [m][kperm] (reused)
__device__ __half g_hA[BS * HDIM];                // h ping-pong (fp16, k-PERMUTED)
__device__ __half g_hB[BS * HDIM];
__device__ float  g_c [BS * HDIM];

// monotonic per-CTA step flags (graph-replay safe: base re-read each launch)
__device__ unsigned g_flags[NCTA];

// ---------------- helpers -------------------------------------------------------
__device__ __forceinline__ void mma_f16(float& c0, float& c1, float& c2, float& c3,
                                        unsigned a0, unsigned a1, unsigned a2, unsigned a3,
                                        unsigned b0, unsigned b1) {
    asm volatile(
        "mma.sync.aligned.m16n8k16.row.col.f32.f16.f16.f32 "
        "{%0,%1,%2,%3}, {%4,%5,%6,%7}, {%8,%9}, {%0,%1,%2,%3};"
        : "+f"(c0), "+f"(c1), "+f"(c2), "+f"(c3)
        : "r"(a0), "r"(a1), "r"(a2), "r"(a3), "r"(b0), "r"(b1));
}

__device__ __forceinline__ float sigmoidf_(float x) {
    return 1.0f / (1.0f + __expf(-x));
}

__device__ __forceinline__ unsigned ld_acq(const unsigned* p) {
    unsigned v;
    asm volatile("ld.acquire.gpu.global.u32 %0, [%1];" : "=r"(v) : "l"(p) : "memory");
    return v;
}
__device__ __forceinline__ void st_rel(unsigned* p, unsigned v) {
    asm volatile("st.release.gpu.global.u32 [%0], %1;" :: "l"(p), "r"(v) : "memory");
}

__device__ __forceinline__ void cpa16(void* s, const void* g) {
    unsigned sa = (unsigned)__cvta_generic_to_shared(s);
    asm volatile("cp.async.cg.shared.global [%0], [%1], 16;" :: "r"(sa), "l"(g));
}
__device__ __forceinline__ void cpa_commit() {
    asm volatile("cp.async.commit_group;");
}
__device__ __forceinline__ void cpa_wait1() {
    asm volatile("cp.async.wait_group 1;");
}

// fp16 k-permutation within each 32-k block: lane tg's 8 halves for two k16
// MMA tiles become one contiguous 16B vector.
// pos = tg*8 + tile*4 + c*2 + b  where k%32 = tile*16 + c*8 + 2*tg + b
__device__ __host__ __forceinline__ int hperm16(int k) {
    int t = k & 31;
    int tile = t >> 4;
    int u = t & 15;
    int b = u & 1;
    int tg = (u >> 1) & 3;
    int c = u >> 3;
    return (k & ~31) | (tg * 8 + tile * 4 + c * 2 + b);
}

// ---------------- packing / conversion kernels ------------------------------------
// A conversion: fp32 [m][k] -> fp16 [m][hperm16(k)]; 2 elems/thread (k even pairs)
__global__ void cvtA(const float* __restrict__ src, __half* __restrict__ dst, int total) {
    int i2 = blockIdx.x * blockDim.x + threadIdx.x;
    int idx = i2 * 2;
    if (idx >= total) return;
    float2 v = *reinterpret_cast<const float2*>(src + idx);
    int m = idx >> 10, k = idx & 1023;
    *reinterpret_cast<__half2*>(dst + ((size_t)m << 10) + hperm16(k)) =
        __floats2half2_rn(v.x, v.y);
}

// W transpose+permute pack: dst[(j*4+gate)][hperm16(k)] = fp16(W_gate[k][j])
__global__ void pack_wt(const float* __restrict__ Wi, const float* __restrict__ Wf,
                        const float* __restrict__ Wg, const float* __restrict__ Wo,
                        __half* __restrict__ dst) {
    const float* W = (blockIdx.z == 0) ? Wi : (blockIdx.z == 1) ? Wf
                   : (blockIdx.z == 2) ? Wg : Wo;
    __shared__ __half tile[64][65];
    const int k0 = blockIdx.x * 64, j0 = blockIdx.y * 64;
    const int tid = threadIdx.x;
#pragma unroll
    for (int it = 0; it < 16; it++) {
        int v = tid + it * 256;
        int ky = v >> 6, jx = v & 63;
        tile[ky][jx] = __float2half(W[(size_t)(k0 + ky) * HDIM + j0 + jx]);
    }
    __syncthreads();
#pragma unroll
    for (int it = 0; it < 16; it++) {
        int v = tid + it * 256;
        int jy = v >> 6, kx = v & 63;
        int n = (j0 + jy) * 4 + blockIdx.z;
        dst[(size_t)n * KD + hperm16(k0 + kx)] = tile[kx][jy];
    }
}

// recurrent weights: fp32 packed [k][j*4+g] (for the lstm SMEM preload)
__global__ void pack_w(const float* __restrict__ Wi, const float* __restrict__ Wf,
                       const float* __restrict__ Wg, const float* __restrict__ Wo,
                       float* __restrict__ dst) {
    int idx = blockIdx.x * blockDim.x + threadIdx.x;
    if (idx >= HDIM * HDIM) return;
    float4 v;
    v.x = Wi[idx]; v.y = Wf[idx]; v.z = Wg[idx]; v.w = Wo[idx];
    reinterpret_cast<float4*>(dst)[idx] = v;
}

__global__ void pack_b(const float* __restrict__ bi, const float* __restrict__ bf,
                       const float* __restrict__ bg, const float* __restrict__ bo,
                       float* __restrict__ dst) {
    int j = blockIdx.x * blockDim.x + threadIdx.x;
    if (j >= HDIM) return;
    float4 v;
    v.x = bi[j]; v.y = bf[j]; v.z = bg[j]; v.w = bo[j];
    reinterpret_cast<float4*>(dst)[j] = v;
}

// ---------------- big input-projection GEMM (fp16, cp.async 2-stage) -------------
// C[M,4096] = A[M,1024] @ B^T + bias. A fp16 [m][kperm], B fp16 [n][kperm].
// Tiles 128x128x64; 256 threads = 8 warps (2M x 4N), warp tile 64x32.
#define GSTR 96                       // SMEM row stride (halves): 48 words, cf-free
#define GSTAGE (128 * GSTR)           // halves per matrix per stage

__global__ void __launch_bounds__(256, 2)
gemm_xw_f16(const __half* __restrict__ A, const __half* __restrict__ B,
            float* __restrict__ C, const float* __restrict__ bias) {
    extern __shared__ __align__(16) __half gs[];
    // [stage0 A][stage1 A][stage0 B][stage1 B]
    const int m0 = blockIdx.y * 128;
    const int n0 = blockIdx.x * 128;
    const int tid  = threadIdx.x;
    const int warp = tid >> 5, lane = tid & 31;
    const int grp  = lane >> 2, tg = lane & 3;
    const int wm = warp & 1;          // M half (64 rows)
    const int wn = warp >> 1;         // N quarter (32 cols)

    const int cc = tid & 7;           // chunk (16B) within row
    const int rr = tid >> 3;          // base row (32 rows per iter)

    auto issue = [&](int st, int kofs) {
        __half* As = gs + st * GSTAGE;
        __half* Bs = gs + 2 * GSTAGE + st * GSTAGE;
#pragma unroll
        for (int i = 0; i < 4; i++) {
            int row = rr + i * 32;
            cpa16(As + row * GSTR + cc * 8,
                  A + (size_t)(m0 + row) * KD + kofs + cc * 8);
            cpa16(Bs + row * GSTR + cc * 8,
                  B + (size_t)(n0 + row) * KD + kofs + cc * 8);
        }
        cpa_commit();
    };

    issue(0, 0);
    issue(1, 64);

    float acc[4][4][4];
#pragma unroll
    for (int mi = 0; mi < 4; mi++)
#pragma unroll
        for (int ni = 0; ni < 4; ni++)
#pragma unroll
            for (int q = 0; q < 4; q++) acc[mi][ni][q] = 0.0f;

    for (int kt = 0; kt < 16; kt++) {
        cpa_wait1();
        __syncthreads();
        const __half* As = gs + (kt & 1) * GSTAGE;
        const __half* Bs = gs + 2 * GSTAGE + (kt & 1) * GSTAGE;

#pragma unroll
        for (int g32 = 0; g32 < 2; g32++) {
            const int ko = g32 * 32 + tg * 8;
            uint4 Bf[4];
#pragma unroll
            for (int ni = 0; ni < 4; ni++) {
                const int c = wn * 32 + ni * 8 + grp;
                Bf[ni] = *reinterpret_cast<const uint4*>(Bs + c * GSTR + ko);
            }
#pragma unroll
            for (int mi = 0; mi < 4; mi++) {
                const int r = wm * 64 + mi * 16 + grp;
                uint4 Aa = *reinterpret_cast<const uint4*>(As + (r    ) * GSTR + ko);
                uint4 Ab = *reinterpret_cast<const uint4*>(As + (r + 8) * GSTR + ko);
#pragma unroll
                for (int ni = 0; ni < 4; ni++) {
                    mma_f16(acc[mi][ni][0], acc[mi][ni][1], acc[mi][ni][2], acc[mi][ni][3],
                            Aa.x, Ab.x, Aa.y, Ab.y, Bf[ni].x, Bf[ni].y);
                    mma_f16(acc[mi][ni][0], acc[mi][ni][1], acc[mi][ni][2], acc[mi][ni][3],
                            Aa.z, Ab.z, Aa.w, Ab.w, Bf[ni].z, Bf[ni].w);
                }
            }
        }
        __syncthreads();
        if (kt < 14) issue(kt & 1, (kt + 2) * 64);
        else cpa_commit();            // keep group accounting uniform
    }

    // epilogue: + bias, write fp32
#pragma unroll
    for (int mi = 0; mi < 4; mi++) {
        const int r = m0 + wm * 64 + mi * 16 + grp;
#pragma unroll
        for (int ni = 0; ni < 4; ni++) {
            const int c = n0 + wn * 32 + ni * 8 + tg * 2;
            float2 bv = *reinterpret_cast<const float2*>(bias + c);
            float2 o0, o1;
            o0.x = acc[mi][ni][0] + bv.x;  o0.y = acc[mi][ni][1] + bv.y;
            o1.x = acc[mi][ni][2] + bv.x;  o1.y = acc[mi][ni][3] + bv.y;
            *reinterpret_cast<float2*>(C + (size_t)r * G4 + c)       = o0;
            *reinterpret_cast<float2*>(C + (size_t)(r + 8) * G4 + c) = o1;
        }
    }
}
#define GEMM_SMEM (4 * GSTAGE * (int)sizeof(__half))   // 96 KB

// ---------------- persistent recurrent layer (fp16 MMA) ---------------------------
#define WT_STRIDE 1056
#define PS_STRIDE 36
#define SMEM_BYTES (32 * WT_STRIDE * 2 + 4 * 64 * PS_STRIDE * 4)

template <bool SEQ16>
__global__ void __launch_bounds__(NTHR, 1)
lstm_layer(const float* __restrict__ xw, __half* __restrict__ h0,
           __half* __restrict__ h1, float* __restrict__ cdump,
           float* __restrict__ seq32, __half* __restrict__ seq16) {
    extern __shared__ __align__(16) unsigned char smem_raw[];
    __half* Wt = reinterpret_cast<__half*>(smem_raw);
    float*  Ps = reinterpret_cast<float*>(smem_raw + 32 * WT_STRIDE * 2);

    const int tid  = threadIdx.x;
    const int warp = tid >> 5, lane = tid & 31;
    const int grp  = lane >> 2, tg = lane & 3;
    const int wm = warp & 1;
    const int ks = warp >> 1;

    const int n0 = blockIdx.x * 32;
    const int J0 = blockIdx.x * 8;

    const unsigned base = g_flags[blockIdx.x];

    for (int idx = tid; idx < 32 * 1024; idx += NTHR) {
        int c = idx & 31, k = idx >> 5;
        Wt[c * WT_STRIDE + hperm16(k)] = __float2half(g_Wh[(size_t)k * G4 + n0 + c]);
    }
    for (int idx = tid; idx < 512; idx += NTHR) {
        int b = idx >> 3, j = idx & 7;
        int p = b * HDIM + hperm16(J0 + j);
        h0[p] = __float2half(0.0f);
        h1[p] = __float2half(0.0f);
    }

    __syncthreads();
    if (tid == 0) st_rel(&g_flags[blockIdx.x], base + 1);

    float creg[2] = {0.0f, 0.0f};
    __half* hbuf[2] = {h0, h1};

    const int r0 = wm * 32 + grp;
    const int kbase = ks * 256;

    for (int s = 0; s < SEQ; s++) {
        const __half* __restrict__ hr = hbuf[s & 1];
        __half* __restrict__ hw = hbuf[(s + 1) & 1];

        const float* xw_t = xw + (size_t)s * BS * G4;
        float4 xv[2];
#pragma unroll
        for (int it = 0; it < 2; it++) {
            int idx = tid + it * NTHR;
            int b = idx >> 3, col = (idx & 7) << 2;
            xv[it] = *reinterpret_cast<const float4*>(xw_t + (size_t)b * G4 + n0 + col);
        }

        {
            const unsigned target = base + 1 + (unsigned)s;
            bool ok;
            do {
                unsigned v = (tid < NCTA) ? ld_acq(&g_flags[tid]) : target;
                ok = (int)(v - target) >= 0;
            } while (!__syncthreads_and(ok));
        }

        float acc[2][4][4];
#pragma unroll
        for (int mt = 0; mt < 2; mt++)
#pragma unroll
            for (int nt = 0; nt < 4; nt++)
#pragma unroll
                for (int q = 0; q < 4; q++) acc[mt][nt][q] = 0.0f;

        const __half* hA0 = hr + (size_t)(r0     ) * KD + kbase + tg * 8;
        const __half* hA1 = hr + (size_t)(r0 +  8) * KD + kbase + tg * 8;
        const __half* hA2 = hr + (size_t)(r0 + 16) * KD + kbase + tg * 8;
        const __half* hA3 = hr + (size_t)(r0 + 24) * KD + kbase + tg * 8;

        uint4 A0 = *reinterpret_cast<const uint4*>(hA0);
        uint4 A1 = *reinterpret_cast<const uint4*>(hA1);
        uint4 A2 = *reinterpret_cast<const uint4*>(hA2);
        uint4 A3 = *reinterpret_cast<const uint4*>(hA3);

#pragma unroll
        for (int g = 0; g < 8; g++) {
            uint4 P0, P1, P2, P3;
            if (g < 7) {
                const int off = (g + 1) * 32;
                P0 = *reinterpret_cast<const uint4*>(hA0 + off);
                P1 = *reinterpret_cast<const uint4*>(hA1 + off);
                P2 = *reinterpret_cast<const uint4*>(hA2 + off);
                P3 = *reinterpret_cast<const uint4*>(hA3 + off);
            }
            uint4 Bv[4];
#pragma unroll
            for (int nt = 0; nt < 4; nt++) {
                const int c = nt * 8 + grp;
                Bv[nt] = *reinterpret_cast<const uint4*>(
                    Wt + c * WT_STRIDE + kbase + g * 32 + tg * 8);
            }
#pragma unroll
            for (int nt = 0; nt < 4; nt++) {
                mma_f16(acc[0][nt][0], acc[0][nt][1], acc[0][nt][2], acc[0][nt][3],
                        A0.x, A1.x, A0.y, A1.y, Bv[nt].x, Bv[nt].y);
                mma_f16(acc[1][nt][0], acc[1][nt][1], acc[1][nt][2], acc[1][nt][3],
                        A2.x, A3.x, A2.y, A3.y, Bv[nt].x, Bv[nt].y);
            }
#pragma unroll
            for (int nt = 0; nt < 4; nt++) {
                mma_f16(acc[0][nt][0], acc[0][nt][1], acc[0][nt][2], acc[0][nt][3],
                        A0.z, A1.z, A0.w, A1.w, Bv[nt].z, Bv[nt].w);
                mma_f16(acc[1][nt][0], acc[1][nt][1], acc[1][nt][2], acc[1][nt][3],
                        A2.z, A3.z, A2.w, A3.w, Bv[nt].z, Bv[nt].w);
            }
            A0 = P0; A1 = P1; A2 = P2; A3 = P3;
        }

        {
            float* P = Ps + ks * 64 * PS_STRIDE;
#pragma unroll
            for (int mt = 0; mt < 2; mt++) {
                const int r = wm * 32 + mt * 16 + grp;
#pragma unroll
                for (int nt = 0; nt < 4; nt++) {
                    const int c = nt * 8 + tg * 2;
                    *reinterpret_cast<float2*>(P + (r    ) * PS_STRIDE + c) =
                        make_float2(acc[mt][nt][0], acc[mt][nt][1]);
                    *reinterpret_cast<float2*>(P + (r + 8) * PS_STRIDE + c) =
                        make_float2(acc[mt][nt][2], acc[mt][nt][3]);
                }
            }
        }
        __syncthreads();

#pragma unroll
        for (int it = 0; it < 2; it++) {
            int idx = tid + it * NTHR;
            int b = idx >> 3, j = idx & 7;
            int col = j << 2;
            float4 p0 = *reinterpret_cast<const float4*>(Ps + 0 * 64 * PS_STRIDE + b * PS_STRIDE + col);
            float4 p1 = *reinterpret_cast<const float4*>(Ps + 1 * 64 * PS_STRIDE + b * PS_STRIDE + col);
            float4 p2 = *reinterpret_cast<const float4*>(Ps + 2 * 64 * PS_STRIDE + b * PS_STRIDE + col);
            float4 p3 = *reinterpret_cast<const float4*>(Ps + 3 * 64 * PS_STRIDE + b * PS_STRIDE + col);

            float pi  = xv[it].x + ((p0.x + p1.x) + (p2.x + p3.x));
            float pfv = xv[it].y + ((p0.y + p1.y) + (p2.y + p3.y));
            float pg  = xv[it].z + ((p0.z + p1.z) + (p2.z + p3.z));
            float po  = xv[it].w + ((p0.w + p1.w) + (p2.w + p3.w));

            float gi = sigmoidf_(pi);
            float gf = sigmoidf_(pfv);
            float gg = tanhf(pg);
            float go = sigmoidf_(po);

            float cv = gf * creg[it] + gi * gg;
            creg[it] = cv;
            float hv = go * tanhf(cv);
            __half hvh = __float2half(hv);

            int J = J0 + j;
            hw[b * HDIM + hperm16(J)] = hvh;
            if constexpr (SEQ16) {
                seq16[((size_t)s * BS + b) * HDIM + hperm16(J)] = hvh;
            } else {
                seq32[((size_t)s * BS + b) * HDIM + J] = hv;
            }
            if (s == SEQ - 1) cdump[b * HDIM + J] = cv;
        }

        __syncthreads();
        if (tid == 0) st_rel(&g_flags[blockIdx.x], base + 2 + (unsigned)s);
    }
}

// ---------------- tail: (h, c) after the sequence --------------------------------
__global__ void copy_tail(const float* __restrict__ hsrc, const float* __restrict__ csrc,
                          float* __restrict__ dst) {
    int i = blockIdx.x * blockDim.x + threadIdx.x;
    if (i < BS * HDIM) {
        dst[i] = hsrc[i];
        dst[BS * HDIM + i] = csrc[i];
    }
}

// ---------------- launcher --------------------------------------------------------
extern "C" void kernel_launch(void* const* d_in, const int* in_sizes, int n_in,
                              void* d_out, int out_size) {
    (void)in_sizes; (void)n_in;

    const float* x     = (const float*)d_in[0];
    const float* Wii0  = (const float*)d_in[1];
    const float* Wii   = (const float*)d_in[2];
    const float* Whi   = (const float*)d_in[3];
    const float* Wif0  = (const float*)d_in[4];
    const float* Wif   = (const float*)d_in[5];
    const float* Whf   = (const float*)d_in[6];
    const float* Wig0  = (const float*)d_in[7];
    const float* Wig   = (const float*)d_in[8];
    const float* Whg   = (const float*)d_in[9];
    const float* Wio0  = (const float*)d_in[10];
    const float* Wio   = (const float*)d_in[11];
    const float* Who   = (const float*)d_in[12];
    const float* bi    = (const float*)d_in[13];
    const float* bf    = (const float*)d_in[14];
    const float* bg    = (const float*)d_in[15];
    const float* bo    = (const float*)d_in[16];

    float *pWh, *pBias, *pXw, *pC;
    __half *pWx0h, *pWx1h, *pAh, *pHA, *pHB;
    cudaGetSymbolAddress((void**)&pWx0h, g_Wx0h);
    cudaGetSymbolAddress((void**)&pWx1h, g_Wx1h);
    cudaGetSymbolAddress((void**)&pWh,   g_Wh);
    cudaGetSymbolAddress((void**)&pBias, g_bias);
    cudaGetSymbolAddress((void**)&pXw,   g_xw);
    cudaGetSymbolAddress((void**)&pAh,   g_Ah);
    cudaGetSymbolAddress((void**)&pHA,   g_hA);
    cudaGetSymbolAddress((void**)&pHB,   g_hB);
    cudaGetSymbolAddress((void**)&pC,    g_c);

    float* out = (float*)d_out;

    static bool attr_set = false;
    if (!attr_set) {
        cudaFuncSetAttribute(lstm_layer<true>,
                             cudaFuncAttributeMaxDynamicSharedMemorySize, SMEM_BYTES);
        cudaFuncSetAttribute(lstm_layer<false>,
                             cudaFuncAttributeMaxDynamicSharedMemorySize, SMEM_BYTES);
        cudaFuncSetAttribute(gemm_xw_f16,
                             cudaFuncAttributeMaxDynamicSharedMemorySize, GEMM_SMEM);
        attr_set = true;
    }

    // pack / convert
    {
        int n = SEQ * BS * IN_DIM;
        cvtA<<<(n / 2 + 255) / 256, 256>>>(x, pAh, n);
        pack_wt<<<dim3(16, 16, 4), 256>>>(Wii0, Wif0, Wig0, Wio0, pWx0h);
        pack_wt<<<dim3(16, 16, 4), 256>>>(Wii,  Wif,  Wig,  Wio,  pWx1h);
        int m = HDIM * HDIM;
        pack_w<<<(m + 255) / 256, 256>>>(Whi, Whf, Whg, Who, pWh);
        pack_b<<<(HDIM + 255) / 256, 256>>>(bi, bf, bg, bo, pBias);
    }

    const dim3 gemm_grid(G4 / 128, (SEQ * BS) / 128);  // (32, 256)

    // ---------------- layer 0 ----------------
    gemm_xw_f16<<<gemm_grid, 256, GEMM_SMEM>>>(pAh, pWx0h, pXw, pBias);
    lstm_layer<true><<<NCTA, NTHR, SMEM_BYTES>>>(pXw, pHA, pHB, pC, nullptr, pAh);

    // ---------------- layer 1 ----------------
    gemm_xw_f16<<<gemm_grid, 256, GEMM_SMEM>>>(pAh, pWx1h, pXw, pBias);
    lstm_layer<false><<<NCTA, NTHR, SMEM_BYTES>>>(pXw, pHA, pHB, pC, out, nullptr);

    // tail: final (h, c). h final = seq output at t = SEQ-1 (full precision).
    size_t seqN = (size_t)SEQ * BS * HDIM;
    if ((size_t)out_size >= seqN + 2 * (size_t)BS * HDIM) {
        copy_tail<<<(BS * HDIM + 255) / 256, 256>>>(out + seqN - (size_t)BS * HDIM,
                                                    pC, out + seqN);
    }
}